// round 2
// baseline (speedup 1.0000x reference)
#include <cuda_runtime.h>
#include <cstdint>

// QConv2d binarized conv: x(32,64,128,128) f32, w(64,64,3,3) OIHW,
// stride=2, pad=1 -> out(32,64,64,64) f32.
// sign-binarize both; conv == 576 - 2*popcount(xor) with border correction.

#define NB 32
#define CIN 64
#define H 128
#define W 128
#define OC 64
#define OH 64
#define OW 64

// Scratch (device globals: allocation-free per harness rules)
__device__ unsigned long long g_xbits[NB * H * W];   // 4 MB: channel-packed sign bits
__device__ unsigned long long g_wpack[OC * 10];      // 9 taps + 1 pad word per o (80B stride)
__device__ float              g_corr[4 * OC];        // border corrections per mask class

// ---------------------------------------------------------------------------
// Pack x: NCHW f32 -> per-(n,h,w) uint64 of sign bits over c.
// Thread handles 4 consecutive w positions; per-c float4 loads are fully
// coalesced (warp covers 512B contiguous per iteration).
// ---------------------------------------------------------------------------
__global__ void __launch_bounds__(256) pack_x_kernel(const float* __restrict__ x) {
    int g = blockIdx.x * blockDim.x + threadIdx.x;   // 0 .. 131071
    int w4 = (g & 31) * 4;                           // 4-wide w group
    int h  = (g >> 5) & 127;
    int n  = g >> 12;

    const float* base = x + ((long)n * CIN * H * W) + (long)h * W + w4;

    unsigned long long b0 = 0, b1 = 0, b2 = 0, b3 = 0;
#pragma unroll 16
    for (int c = 0; c < CIN; c++) {
        float4 v = *reinterpret_cast<const float4*>(base + (long)c * (H * W));
        b0 |= (unsigned long long)(v.x >= 0.0f) << c;
        b1 |= (unsigned long long)(v.y >= 0.0f) << c;
        b2 |= (unsigned long long)(v.z >= 0.0f) << c;
        b3 |= (unsigned long long)(v.w >= 0.0f) << c;
    }
    unsigned long long* dst = g_xbits + ((long)n * H + h) * W + w4;
    dst[0] = b0; dst[1] = b1; dst[2] = b2; dst[3] = b3;
}

// ---------------------------------------------------------------------------
// Pack w: OIHW f32 -> g_wpack[o*10 + t] (t = kh*3+kw), plus border
// correction table. corr[m][o] = sum over invalid taps of (64 - 2*popc(w_t)).
// Mask classes: 0=interior, 1=top row (kh=0 taps), 2=left col (kw=0 taps),
// 3=corner (union).
// ---------------------------------------------------------------------------
__global__ void pack_w_kernel(const float* __restrict__ w) {
    __shared__ int s_pc[OC * 9];
    int tid = threadIdx.x;
    if (tid < OC * 9) {
        int o = tid / 9, t = tid % 9;
        unsigned long long bits = 0;
#pragma unroll 8
        for (int i = 0; i < CIN; i++) {
            float v = w[(o * CIN + i) * 9 + t];
            bits |= (unsigned long long)(v >= 0.0f) << i;
        }
        g_wpack[o * 10 + t] = bits;
        if (t == 0) g_wpack[o * 10 + 9] = 0ull;
        s_pc[o * 9 + t] = __popcll(bits);
    }
    __syncthreads();
    if (tid < OC) {
        int o = tid;
        float term0 = (float)(64 - 2 * s_pc[o * 9 + 0]);
        float c1 = term0 + (float)(64 - 2 * s_pc[o * 9 + 1])
                         + (float)(64 - 2 * s_pc[o * 9 + 2]);
        float c2 = term0 + (float)(64 - 2 * s_pc[o * 9 + 3])
                         + (float)(64 - 2 * s_pc[o * 9 + 6]);
        float c3 = c1 + c2 - term0;
        g_corr[0 * OC + o] = 0.0f;
        g_corr[1 * OC + o] = c1;
        g_corr[2 * OC + o] = c2;
        g_corr[3 * OC + o] = c3;
    }
}

// ---------------------------------------------------------------------------
// Conv: each thread = one (n, oh, ow); loops all 64 output channels.
// xbits for the 9 taps held in registers; wbits read from smem via
// LDS.128 broadcast (all lanes in a warp share o). Branchless borders via
// the correction table. STG per o is coalesced (lanes = consecutive ow).
// Block = 4 oh rows x 64 ow; grid = (16, 32) = 512 CTAs (~1 wave).
// ---------------------------------------------------------------------------
__global__ void __launch_bounds__(256) conv_kernel(float* __restrict__ out) {
    __shared__ unsigned long long ws[OC * 10];
    __shared__ float scorr[4 * OC];

    int tid = threadIdx.x;
    for (int i = tid; i < OC * 10; i += 256) ws[i] = g_wpack[i];
    for (int i = tid; i < 4 * OC; i += 256) scorr[i] = g_corr[i];
    __syncthreads();

    int ow = tid & 63;
    int r  = tid >> 6;
    int oh = blockIdx.x * 4 + r;
    int n  = blockIdx.y;

    const unsigned long long* xb = g_xbits + (long)n * (H * W);
    int ih0 = 2 * oh - 1;
    int iw0 = 2 * ow - 1;

    unsigned long long xw[9];
#pragma unroll
    for (int kh = 0; kh < 3; kh++) {
#pragma unroll
        for (int kw = 0; kw < 3; kw++) {
            int ih = ih0 + kh;
            int iw = iw0 + kw;
            bool valid = (ih >= 0) && (iw >= 0);   // upper bounds never exceeded
            xw[kh * 3 + kw] = valid ? xb[ih * W + iw] : 0ull;
        }
    }

    int mt = ((oh == 0) ? 1 : 0) | ((ow == 0) ? 2 : 0);
    const float* cp = scorr + mt * OC;
    float* op = out + (((long)n * OC) * OH + oh) * OW + ow;

#pragma unroll 4
    for (int o = 0; o < OC; o++) {
        const unsigned long long* wrow = ws + o * 10;
        const ulonglong2* wp = reinterpret_cast<const ulonglong2*>(wrow);
        ulonglong2 wa = wp[0], wb2 = wp[1], wc = wp[2], wd = wp[3];
        unsigned long long we = wrow[8];

        int cnt = __popcll(xw[0] ^ wa.x) + __popcll(xw[1] ^ wa.y)
                + __popcll(xw[2] ^ wb2.x) + __popcll(xw[3] ^ wb2.y)
                + __popcll(xw[4] ^ wc.x) + __popcll(xw[5] ^ wc.y)
                + __popcll(xw[6] ^ wd.x) + __popcll(xw[7] ^ wd.y)
                + __popcll(xw[8] ^ we);

        op[(long)o * (OH * OW)] = 576.0f - 2.0f * (float)cnt - cp[o];
    }
}

// ---------------------------------------------------------------------------
extern "C" void kernel_launch(void* const* d_in, const int* in_sizes, int n_in,
                              void* d_out, int out_size) {
    const float* x = (const float*)d_in[0];
    const float* w = (const float*)d_in[1];
    float* out = (float*)d_out;

    pack_x_kernel<<<512, 256>>>(x);          // 131072 threads, one 4-word group each
    pack_w_kernel<<<1, 576>>>(w);
    conv_kernel<<<dim3(16, 32), 256>>>(out);
}

// round 3
// speedup vs baseline: 1.1110x; 1.1110x over previous
#include <cuda_runtime.h>
#include <cstdint>

// QConv2d binarized conv: x(32,64,128,128) f32, w(64,64,3,3) OIHW,
// stride=2, pad=1 -> out(32,64,64,64) f32.
// sign-binarize both; conv == (576 - corr) - 2*popcount(xor).

#define NB 32
#define CIN 64
#define H 128
#define W 128
#define OC 64
#define OH 64
#define OW 64

// Scratch (device globals: allocation-free per harness rules)
// Split bit planes: lo = channels 0..31, hi = channels 32..63.
__device__ unsigned int       g_xlo[NB * H * W];     // 2 MB
__device__ unsigned int       g_xhi[NB * H * W];     // 2 MB
__device__ unsigned long long g_wpack[OC * 10];      // 9 taps + pad per o (80B stride)
__device__ float              g_corr2[4 * OC];       // 576 - border correction

// ---------------------------------------------------------------------------
// Pack x: each thread packs 32 channels (one plane half) for 4 consecutive w.
// 262144 threads; per-c loads are float4, warp-coalesced (2x256B per LDG.128
// warp op); output is one STG.128 per thread into its plane.
// ---------------------------------------------------------------------------
__global__ void __launch_bounds__(256) pack_x_kernel(const float* __restrict__ x) {
    int g = blockIdx.x * blockDim.x + threadIdx.x;   // 0 .. 262143
    int half = g & 1;                                // 0: c0-31, 1: c32-63
    int w4   = ((g >> 1) & 31) * 4;
    int h    = (g >> 6) & 127;
    int n    = g >> 13;

    const float* base = x + ((long)(n * CIN + half * 32) * H + h) * W + w4;

    unsigned int b0 = 0, b1 = 0, b2 = 0, b3 = 0;
#pragma unroll 16
    for (int c = 0; c < 32; c++) {
        float4 v = *reinterpret_cast<const float4*>(base + (long)c * (H * W));
        b0 |= (unsigned int)(v.x >= 0.0f) << c;
        b1 |= (unsigned int)(v.y >= 0.0f) << c;
        b2 |= (unsigned int)(v.z >= 0.0f) << c;
        b3 |= (unsigned int)(v.w >= 0.0f) << c;
    }
    unsigned int* plane = half ? g_xhi : g_xlo;
    uint4 val; val.x = b0; val.y = b1; val.z = b2; val.w = b3;
    *reinterpret_cast<uint4*>(plane + ((long)(n * H + h) * W + w4)) = val;
}

// ---------------------------------------------------------------------------
// Pack w: one block per output channel o; 64 threads = 64 input channels.
// Ballot packs the sign bits; thread 0 builds the border table.
// ---------------------------------------------------------------------------
__global__ void __launch_bounds__(64) pack_w_kernel(const float* __restrict__ w) {
    __shared__ unsigned int s_lo[9], s_hi[9];
    __shared__ int s_pc[9];
    int o = blockIdx.x;
    int i = threadIdx.x;            // input channel
    int warp = i >> 5;
    int lane = i & 31;

    const float* wr = w + (o * CIN + i) * 9;
    float v[9];
#pragma unroll
    for (int t = 0; t < 9; t++) v[t] = wr[t];

#pragma unroll
    for (int t = 0; t < 9; t++) {
        unsigned int m = __ballot_sync(0xFFFFFFFFu, v[t] >= 0.0f);
        if (lane == 0) {
            if (warp == 0) s_lo[t] = m; else s_hi[t] = m;
        }
    }
    __syncthreads();
    if (i < 9) {
        unsigned long long bits =
            (unsigned long long)s_lo[i] | ((unsigned long long)s_hi[i] << 32);
        g_wpack[o * 10 + i] = bits;
        s_pc[i] = __popcll(bits);
    }
    if (i == 9) g_wpack[o * 10 + 9] = 0ull;
    __syncthreads();
    if (i == 0) {
        float term0 = (float)(64 - 2 * s_pc[0]);
        float c1 = term0 + (float)(64 - 2 * s_pc[1]) + (float)(64 - 2 * s_pc[2]);
        float c2 = term0 + (float)(64 - 2 * s_pc[3]) + (float)(64 - 2 * s_pc[6]);
        float c3 = c1 + c2 - term0;
        g_corr2[0 * OC + o] = 576.0f;
        g_corr2[1 * OC + o] = 576.0f - c1;
        g_corr2[2 * OC + o] = 576.0f - c2;
        g_corr2[3 * OC + o] = 576.0f - c3;
    }
}

// ---------------------------------------------------------------------------
// Conv: each thread computes TWO outputs (n, oh, ow=lane) and (n, oh, lane+32),
// looping all 64 output channels. Weight words come from smem (LDS.128
// broadcast, shared by both outputs); x tap words live in registers as
// 32-bit plane halves. Branchless borders via 576-corr table.
// Block = 128 threads (4 oh rows x 32 lanes); grid = (16, 32) = 512 CTAs.
// ---------------------------------------------------------------------------
__global__ void __launch_bounds__(128) conv_kernel(float* __restrict__ out) {
    __shared__ unsigned long long ws[OC * 10];
    __shared__ float scorr[4 * OC];

    int tid = threadIdx.x;
    for (int i = tid; i < OC * 10; i += 128) ws[i] = g_wpack[i];
    for (int i = tid; i < 4 * OC; i += 128) scorr[i] = g_corr2[i];
    __syncthreads();

    int lane = tid & 31;
    int r    = tid >> 5;
    int oh   = blockIdx.x * 4 + r;
    int n    = blockIdx.y;

    const unsigned int* xl = g_xlo + (long)n * (H * W);
    const unsigned int* xh = g_xhi + (long)n * (H * W);

    int ih0  = 2 * oh - 1;
    int iwa0 = 2 * lane - 1;            // output a: ow = lane
    int iwb0 = 2 * (lane + 32) - 1;     // output b: ow = lane+32 (always >= 63)

    unsigned int alo[9], ahi[9], blo[9], bhi[9];
#pragma unroll
    for (int kh = 0; kh < 3; kh++) {
#pragma unroll
        for (int kw = 0; kw < 3; kw++) {
            int t  = kh * 3 + kw;
            int ih = ih0 + kh;
            bool vr = (ih >= 0);
            int iwa = iwa0 + kw;
            bool va = vr && (iwa >= 0);
            int ia  = ih * W + iwa;
            alo[t] = va ? xl[ia] : 0u;
            ahi[t] = va ? xh[ia] : 0u;
            int ib  = ih * W + iwb0 + kw;
            blo[t] = vr ? xl[ib] : 0u;
            bhi[t] = vr ? xh[ib] : 0u;
        }
    }

    int mta = ((oh == 0) ? 1 : 0) | ((lane == 0) ? 2 : 0);
    int mtb = (oh == 0) ? 1 : 0;
    const float* cpa = scorr + mta * OC;
    const float* cpb = scorr + mtb * OC;
    float* op = out + (((long)n * OC) * OH + oh) * OW;

#pragma unroll 4
    for (int o = 0; o < OC; o++) {
        const ulonglong2* wp = reinterpret_cast<const ulonglong2*>(ws + o * 10);
        ulonglong2 q0 = wp[0], q1 = wp[1], q2 = wp[2], q3 = wp[3];
        unsigned long long q4 = ws[o * 10 + 8];
        unsigned long long wt[9] = {q0.x, q0.y, q1.x, q1.y, q2.x, q2.y, q3.x, q3.y, q4};

        int ca = 0, cb = 0;
#pragma unroll
        for (int t = 0; t < 9; t++) {
            unsigned int wl = (unsigned int)wt[t];
            unsigned int wh = (unsigned int)(wt[t] >> 32);
            ca += __popc(alo[t] ^ wl) + __popc(ahi[t] ^ wh);
            cb += __popc(blo[t] ^ wl) + __popc(bhi[t] ^ wh);
        }
        float* po = op + (long)o * (OH * OW);
        po[lane]      = fmaf(-2.0f, (float)ca, cpa[o]);
        po[lane + 32] = fmaf(-2.0f, (float)cb, cpb[o]);
    }
}

// ---------------------------------------------------------------------------
extern "C" void kernel_launch(void* const* d_in, const int* in_sizes, int n_in,
                              void* d_out, int out_size) {
    const float* x = (const float*)d_in[0];
    const float* w = (const float*)d_in[1];
    float* out = (float*)d_out;

    pack_x_kernel<<<1024, 256>>>(x);
    pack_w_kernel<<<64, 64>>>(w);
    conv_kernel<<<dim3(16, 32), 128>>>(out);
}

// round 4
// speedup vs baseline: 1.2063x; 1.0857x over previous
#include <cuda_runtime.h>
#include <cstdint>

// QConv2d binarized conv: x(32,64,128,128) f32, w(64,64,3,3) OIHW,
// stride=2, pad=1 -> out(32,64,64,64) f32.
// sign-binarize both; conv == (576 - corr) - 2*popcount(xor).

#define NB 32
#define CIN 64
#define H 128
#define W 128
#define OC 64
#define OH 64
#define OW 64

// Scratch (device globals: allocation-free per harness rules)
// Split bit planes: lo = channels 0..31, hi = channels 32..63.
__device__ unsigned int       g_xlo[NB * H * W];     // 2 MB
__device__ unsigned int       g_xhi[NB * H * W];     // 2 MB
__device__ unsigned long long g_wpack[OC * 10];      // 9 taps + pad per o (80B stride)
__device__ float              g_corr2[4 * OC];       // 576 - border correction

// ---------------------------------------------------------------------------
// Pack x: each thread packs 32 channels (one plane half) for 4 consecutive w.
// (unchanged from R3: 23.6us, 71.7% DRAM)
// ---------------------------------------------------------------------------
__global__ void __launch_bounds__(256) pack_x_kernel(const float* __restrict__ x) {
    int g = blockIdx.x * blockDim.x + threadIdx.x;   // 0 .. 262143
    int half = g & 1;                                // 0: c0-31, 1: c32-63
    int w4   = ((g >> 1) & 31) * 4;
    int h    = (g >> 6) & 127;
    int n    = g >> 13;

    const float* base = x + ((long)(n * CIN + half * 32) * H + h) * W + w4;

    unsigned int b0 = 0, b1 = 0, b2 = 0, b3 = 0;
#pragma unroll 16
    for (int c = 0; c < 32; c++) {
        float4 v = *reinterpret_cast<const float4*>(base + (long)c * (H * W));
        b0 |= (unsigned int)(v.x >= 0.0f) << c;
        b1 |= (unsigned int)(v.y >= 0.0f) << c;
        b2 |= (unsigned int)(v.z >= 0.0f) << c;
        b3 |= (unsigned int)(v.w >= 0.0f) << c;
    }
    unsigned int* plane = half ? g_xhi : g_xlo;
    uint4 val; val.x = b0; val.y = b1; val.z = b2; val.w = b3;
    *reinterpret_cast<uint4*>(plane + ((long)(n * H + h) * W + w4)) = val;
}

// ---------------------------------------------------------------------------
// Pack w: one block per output channel o; 64 threads = 64 input channels.
// Ballot packs the sign bits; thread 0 builds the (576 - border corr) table.
// ---------------------------------------------------------------------------
__global__ void __launch_bounds__(64) pack_w_kernel(const float* __restrict__ w) {
    __shared__ unsigned int s_lo[9], s_hi[9];
    __shared__ int s_pc[9];
    int o = blockIdx.x;
    int i = threadIdx.x;            // input channel
    int warp = i >> 5;
    int lane = i & 31;

    const float* wr = w + (o * CIN + i) * 9;
    float v[9];
#pragma unroll
    for (int t = 0; t < 9; t++) v[t] = wr[t];

#pragma unroll
    for (int t = 0; t < 9; t++) {
        unsigned int m = __ballot_sync(0xFFFFFFFFu, v[t] >= 0.0f);
        if (lane == 0) {
            if (warp == 0) s_lo[t] = m; else s_hi[t] = m;
        }
    }
    __syncthreads();
    if (i < 9) {
        unsigned long long bits =
            (unsigned long long)s_lo[i] | ((unsigned long long)s_hi[i] << 32);
        g_wpack[o * 10 + i] = bits;
        s_pc[i] = __popcll(bits);
    }
    if (i == 9) g_wpack[o * 10 + 9] = 0ull;
    __syncthreads();
    if (i == 0) {
        float term0 = (float)(64 - 2 * s_pc[0]);
        float c1 = term0 + (float)(64 - 2 * s_pc[1]) + (float)(64 - 2 * s_pc[2]);
        float c2 = term0 + (float)(64 - 2 * s_pc[3]) + (float)(64 - 2 * s_pc[6]);
        float c3 = c1 + c2 - term0;
        g_corr2[0 * OC + o] = 576.0f;
        g_corr2[1 * OC + o] = 576.0f - c1;
        g_corr2[2 * OC + o] = 576.0f - c2;
        g_corr2[3 * OC + o] = 576.0f - c3;
    }
}

// ---------------------------------------------------------------------------
// Conv v2: 2x warp parallelism vs R3 at same per-thread ILP.
// Block = 128 threads = 4 warps: (2 oh-rows) x (2 o-halves). Each thread
// computes TWO spatial outputs (ow=lane, ow=lane+32) over 32 output channels.
// Grid (32, 32) = 1024 CTAs -> 4096 warps (~27/SM).
// Taps in registers (32-bit plane halves); weights via LDS.128 broadcast.
// ---------------------------------------------------------------------------
__global__ void __launch_bounds__(128) conv_kernel(float* __restrict__ out) {
    __shared__ unsigned long long ws[OC * 10];
    __shared__ float scorr[4 * OC];

    int tid = threadIdx.x;
    for (int i = tid; i < OC * 10; i += 128) ws[i] = g_wpack[i];
    for (int i = tid; i < 4 * OC; i += 128) scorr[i] = g_corr2[i];
    __syncthreads();

    int lane  = tid & 31;
    int warp  = tid >> 5;
    int r     = warp & 1;            // oh row within CTA
    int obase = (warp >> 1) * 32;    // o-half
    int oh    = blockIdx.x * 2 + r;
    int n     = blockIdx.y;

    const unsigned int* xl = g_xlo + (long)n * (H * W);
    const unsigned int* xh = g_xhi + (long)n * (H * W);

    int ih0  = 2 * oh - 1;
    int iwa0 = 2 * lane - 1;            // output a: ow = lane
    int iwb0 = 2 * (lane + 32) - 1;     // output b: ow = lane+32 (>= 63, never OOB)

    unsigned int alo[9], ahi[9], blo[9], bhi[9];
#pragma unroll
    for (int kh = 0; kh < 3; kh++) {
#pragma unroll
        for (int kw = 0; kw < 3; kw++) {
            int t  = kh * 3 + kw;
            int ih = ih0 + kh;
            bool vr = (ih >= 0);
            int iwa = iwa0 + kw;
            bool va = vr && (iwa >= 0);
            int ia  = ih * W + iwa;
            alo[t] = va ? xl[ia] : 0u;
            ahi[t] = va ? xh[ia] : 0u;
            int ib  = ih * W + iwb0 + kw;
            blo[t] = vr ? xl[ib] : 0u;
            bhi[t] = vr ? xh[ib] : 0u;
        }
    }

    int mta = ((oh == 0) ? 1 : 0) | ((lane == 0) ? 2 : 0);
    int mtb = (oh == 0) ? 1 : 0;
    const float* cpa = scorr + mta * OC + obase;
    const float* cpb = scorr + mtb * OC + obase;
    float* op = out + (((long)(n * OC + obase)) * OH + oh) * OW;

#pragma unroll 4
    for (int oo = 0; oo < 32; oo++) {
        const unsigned long long* wrow = ws + (obase + oo) * 10;
        const ulonglong2* wp = reinterpret_cast<const ulonglong2*>(wrow);
        ulonglong2 q0 = wp[0], q1 = wp[1], q2 = wp[2], q3 = wp[3];
        unsigned long long q4 = wrow[8];
        unsigned long long wt[9] = {q0.x, q0.y, q1.x, q1.y, q2.x, q2.y, q3.x, q3.y, q4};

        int ca = 0, cb = 0;
#pragma unroll
        for (int t = 0; t < 9; t++) {
            unsigned int wl = (unsigned int)wt[t];
            unsigned int wh = (unsigned int)(wt[t] >> 32);
            ca += __popc(alo[t] ^ wl) + __popc(ahi[t] ^ wh);
            cb += __popc(blo[t] ^ wl) + __popc(bhi[t] ^ wh);
        }
        float* po = op + (long)oo * (OH * OW);
        po[lane]      = fmaf(-2.0f, (float)ca, cpa[oo]);
        po[lane + 32] = fmaf(-2.0f, (float)cb, cpb[oo]);
    }
}

// ---------------------------------------------------------------------------
extern "C" void kernel_launch(void* const* d_in, const int* in_sizes, int n_in,
                              void* d_out, int out_size) {
    const float* x = (const float*)d_in[0];
    const float* w = (const float*)d_in[1];
    float* out = (float*)d_out;

    pack_x_kernel<<<1024, 256>>>(x);
    pack_w_kernel<<<64, 64>>>(w);
    conv_kernel<<<dim3(32, 32), 128>>>(out);
}